// round 9
// baseline (speedup 1.0000x reference)
#include <cuda_runtime.h>
#include <cuda_bf16.h>
#include <cstdint>

// ---------------- problem constants ----------------
#define FAN_IN   128
#define J_DIM    129          // fan_in + bias column
#define N_OUT    128
#define BM       64           // batch rows per CTA iteration (2 m-groups x 32)
#define THREADS  256          // 8 warps: 2(m) x 4(n)
#define GRID_CTAS 296

// Fragment-ordered B operand images (mma.m16n8k16 layout) + bias.
// Index: (((kt*16 + nt)*32 + lane)*2 + reg), halfwords within the u32.
__device__ uint32_t g_Bhi[8 * 16 * 32 * 2];   // 32 KB
__device__ uint32_t g_Blo[8 * 16 * 32 * 2];   // 32 KB
__device__ float    g_bias[N_OUT];

// ======================= kernel 1: gather + split + fragment-pack W ===========
__global__ void gather_convert_kernel(const void* __restrict__ idx_raw,
                                      const float* __restrict__ W) {
    __shared__ int is64_s;
    if (threadIdx.x == 0) {
        // jax int64 silently becomes int32 without x64; detect: little-endian
        // int64 with values < 4096 has every odd 32-bit word zero.
        const int* p = (const int*)idx_raw;
        int any = 0;
        #pragma unroll
        for (int t = 1; t < 129; t += 2) any |= p[t];
        is64_s = (any == 0) ? 1 : 0;
    }
    __syncthreads();
    const int is64 = is64_s;
    const int*       p32 = (const int*)idx_raw;
    const long long* p64 = (const long long*)idx_raw;

    for (int e = threadIdx.x + blockIdx.x * blockDim.x;
         e < N_OUT * J_DIM; e += blockDim.x * gridDim.x) {
        const int n = e / J_DIM;            // output index i
        const int k = e - n * J_DIM;        // reduction index j (128 == bias)
        const long long idx = is64 ? p64[e] : (long long)p32[e];
        const float w = W[idx];
        if (k == FAN_IN) {
            g_bias[n] = w;
        } else {
            const uint32_t bits = __float_as_uint(w);
            const unsigned short hi = (unsigned short)(bits >> 16);
            const float lof = w - __uint_as_float(bits & 0xFFFF0000u);
            const unsigned short lo = __bfloat16_as_ushort(__float2bfloat16(lof));
            const int kt  = k >> 4;          // k-tile (16)
            const int kk  = k & 15;
            const int reg = kk >> 3;         // 0:b0, 1:b1
            const int tig = (kk & 7) >> 1;   // thread-in-group
            const int h   = kk & 1;          // halfword
            const int nt  = n >> 3;          // global n-tile (8)
            const int gid = n & 7;
            const int lane = gid * 4 + tig;
            const int us = ((((kt * 16 + nt) * 32 + lane) * 2 + reg) << 1) + h;
            ((unsigned short*)g_Bhi)[us] = hi;
            ((unsigned short*)g_Blo)[us] = lo;
        }
    }
}

// ======================= mma.sync helper =======================
__device__ __forceinline__ void mma16816(float* c, const uint32_t* a,
                                         uint32_t b0, uint32_t b1) {
    asm volatile(
        "mma.sync.aligned.m16n8k16.row.col.f32.bf16.bf16.f32 "
        "{%0,%1,%2,%3}, {%4,%5,%6,%7}, {%8,%9}, {%0,%1,%2,%3};"
        : "+f"(c[0]), "+f"(c[1]), "+f"(c[2]), "+f"(c[3])
        : "r"(a[0]), "r"(a[1]), "r"(a[2]), "r"(a[3]), "r"(b0), "r"(b1));
}

// ======================= kernel 2: weight-stationary split-bf16 GEMM ==========
// out[b,i] = sum_k a[b,k] * Wm[i,k] + bias[i]
// 8 warps: warp (mg, nw) computes m32 x n32 of each m64 x n128 CTA tile.
// w_hi fragments live in registers for the whole kernel (loaded once);
// the CTA grid-strides over batch tiles.
__global__ __launch_bounds__(THREADS, 1)
void hashed_mma_kernel(const float* __restrict__ A, float* __restrict__ Out,
                       int B, int num_tiles) {
    const int tid  = threadIdx.x;
    const int lane = tid & 31;
    const int wid  = tid >> 5;
    const int nw   = wid & 3;                // n-warp 0..3  (cols nw*32..+32)
    const int mg   = wid >> 2;               // m-group 0..1 (rows mg*32..+32)
    const int gid  = lane >> 2;              // 0..7
    const int tig  = lane & 3;               // 0..3

    // ---- stationary w_hi fragments: one load for the whole kernel ----
    uint2 bh[8][4];
    #pragma unroll
    for (int kt = 0; kt < 8; ++kt)
        #pragma unroll
        for (int nt = 0; nt < 4; ++nt)
            bh[kt][nt] =
                __ldg((const uint2*)&g_Bhi[((kt * 16 + nw * 4 + nt) * 32 + lane) * 2]);

    // w_lo fragment base (read in-loop; small L1-resident working set)
    const uint2* __restrict__ blo_base =
        (const uint2*)&g_Blo[((nw * 4) * 32 + lane) * 2];

    // bias for this warp's columns
    float2 bias[4];
    #pragma unroll
    for (int nt = 0; nt < 4; ++nt)
        bias[nt] = *(const float2*)&g_bias[nw * 32 + nt * 8 + 2 * tig];

    // ---- grid-stride over m-tiles of 64 rows ----
    for (int t = blockIdx.x; t < num_tiles; t += gridDim.x) {
        const int m_base = t * BM + mg * 32;

        const float* arow[2][2];
        bool rok[2][2];
        #pragma unroll
        for (int mt = 0; mt < 2; ++mt)
            #pragma unroll
            for (int rr = 0; rr < 2; ++rr) {
                const int row = m_base + mt * 16 + rr * 8 + gid;
                rok[mt][rr]  = (row < B);
                arow[mt][rr] = A + (long long)row * FAN_IN + 2 * tig;
            }

        float acc[2][4][4];
        #pragma unroll
        for (int mt = 0; mt < 2; ++mt)
            #pragma unroll
            for (int nt = 0; nt < 4; ++nt)
                #pragma unroll
                for (int q = 0; q < 4; ++q) acc[mt][nt][q] = 0.f;

        // A double buffer: v[buf][(mt*2+rr)*2 + {0,1}]
        float2 v[2][8];
        #pragma unroll
        for (int mt = 0; mt < 2; ++mt)
            #pragma unroll
            for (int rr = 0; rr < 2; ++rr) {
                const int q = (mt * 2 + rr) * 2;
                v[0][q]     = rok[mt][rr] ? *(const float2*)(arow[mt][rr])
                                          : make_float2(0.f, 0.f);
                v[0][q + 1] = rok[mt][rr] ? *(const float2*)(arow[mt][rr] + 8)
                                          : make_float2(0.f, 0.f);
            }

        #pragma unroll
        for (int kt = 0; kt < 8; ++kt) {
            const int cur = kt & 1;
            // ---- prefetch next kt's A ----
            if (kt < 7) {
                #pragma unroll
                for (int mt = 0; mt < 2; ++mt)
                    #pragma unroll
                    for (int rr = 0; rr < 2; ++rr) {
                        const int q = (mt * 2 + rr) * 2;
                        const float* ap = arow[mt][rr] + (kt + 1) * 16;
                        v[cur ^ 1][q]     = rok[mt][rr] ? *(const float2*)ap
                                                        : make_float2(0.f, 0.f);
                        v[cur ^ 1][q + 1] = rok[mt][rr] ? *(const float2*)(ap + 8)
                                                        : make_float2(0.f, 0.f);
                    }
            }
            // ---- w_lo fragments for this kt ----
            uint2 bl[4];
            #pragma unroll
            for (int nt = 0; nt < 4; ++nt)
                bl[nt] = __ldg(&blo_base[(kt * 16 + nt) * 32]);

            // ---- in-register fp32 -> bf16 hi/lo split ----
            uint32_t ahi[2][4], alo[2][4];
            #pragma unroll
            for (int mt = 0; mt < 2; ++mt)
                #pragma unroll
                for (int rr = 0; rr < 2; ++rr) {
                    const int q = (mt * 2 + rr) * 2;
                    const float2 v0 = v[cur][q];
                    const float2 v1 = v[cur][q + 1];
                    const uint32_t b00 = __float_as_uint(v0.x);
                    const uint32_t b01 = __float_as_uint(v0.y);
                    const uint32_t b10 = __float_as_uint(v1.x);
                    const uint32_t b11 = __float_as_uint(v1.y);
                    ahi[mt][rr]     = __byte_perm(b00, b01, 0x7632);
                    ahi[mt][rr + 2] = __byte_perm(b10, b11, 0x7632);
                    const float l00 = v0.x - __uint_as_float(b00 & 0xFFFF0000u);
                    const float l01 = v0.y - __uint_as_float(b01 & 0xFFFF0000u);
                    const float l10 = v1.x - __uint_as_float(b10 & 0xFFFF0000u);
                    const float l11 = v1.y - __uint_as_float(b11 & 0xFFFF0000u);
                    asm("cvt.rn.bf16x2.f32 %0, %1, %2;"
                        : "=r"(alo[mt][rr]) : "f"(l01), "f"(l00));
                    asm("cvt.rn.bf16x2.f32 %0, %1, %2;"
                        : "=r"(alo[mt][rr + 2]) : "f"(l11), "f"(l10));
                }

            // ---- 24 MMAs: a_hi*w_hi, a_lo*w_hi, a_hi*w_lo ----
            #pragma unroll
            for (int nt = 0; nt < 4; ++nt) {
                mma16816(acc[0][nt], ahi[0], bh[kt][nt].x, bh[kt][nt].y);
                mma16816(acc[1][nt], ahi[1], bh[kt][nt].x, bh[kt][nt].y);
            }
            #pragma unroll
            for (int nt = 0; nt < 4; ++nt) {
                mma16816(acc[0][nt], alo[0], bh[kt][nt].x, bh[kt][nt].y);
                mma16816(acc[1][nt], alo[1], bh[kt][nt].x, bh[kt][nt].y);
            }
            #pragma unroll
            for (int nt = 0; nt < 4; ++nt) {
                mma16816(acc[0][nt], ahi[0], bl[nt].x, bl[nt].y);
                mma16816(acc[1][nt], ahi[1], bl[nt].x, bl[nt].y);
            }
        }

        // ---- epilogue: + bias, coalesced-sector float2 stores ----
        #pragma unroll
        for (int mt = 0; mt < 2; ++mt) {
            const int row0 = m_base + mt * 16 + gid;
            const int row1 = row0 + 8;
            const bool ok0 = (row0 < B);
            const bool ok1 = (row1 < B);
            float* __restrict__ o0p = Out + (long long)row0 * N_OUT;
            float* __restrict__ o1p = Out + (long long)row1 * N_OUT;
            #pragma unroll
            for (int nt = 0; nt < 4; ++nt) {
                const int col = nw * 32 + nt * 8 + 2 * tig;
                if (ok0) {
                    float2 o0 = make_float2(acc[mt][nt][0] + bias[nt].x,
                                            acc[mt][nt][1] + bias[nt].y);
                    *(float2*)&o0p[col] = o0;
                }
                if (ok1) {
                    float2 o1 = make_float2(acc[mt][nt][2] + bias[nt].x,
                                            acc[mt][nt][3] + bias[nt].y);
                    *(float2*)&o1p[col] = o1;
                }
            }
        }
    }
}

// ======================= launch =======================
extern "C" void kernel_launch(void* const* d_in, const int* in_sizes, int n_in,
                              void* d_out, int out_size) {
    const float* a    = (const float*)d_in[0];
    const float* W    = (const float*)d_in[1];
    const void*  hidx = d_in[2];
    float*       out  = (float*)d_out;

    const int B = in_sizes[0] / FAN_IN;
    const int num_tiles = (B + BM - 1) / BM;

    gather_convert_kernel<<<65, 256>>>(hidx, W);

    const int grid = num_tiles < GRID_CTAS ? num_tiles : GRID_CTAS;
    hashed_mma_kernel<<<grid, THREADS>>>(a, out, B, num_tiles);
}